// round 1
// baseline (speedup 1.0000x reference)
#include <cuda_runtime.h>
#include <cuda_bf16.h>

#define NN 50000
#define EE 1600000
#define DD 128
#define LN_EPS 1e-5f

// ---------------- scratch (static device globals; no runtime allocation) ----
__device__ float g_deg[NN];
__device__ float g_dinv[NN];
__device__ int   g_cnt[NN];
__device__ int   g_rowptr[NN + 1];
__device__ int   g_cursor[NN];
__device__ int   g_src[EE];
__device__ float g_norm[EE];
__device__ float g_xw[(size_t)NN * DD];
__device__ float g_hA[(size_t)NN * DD];
__device__ float g_hB[(size_t)NN * DD];

// ---------------- preprocessing kernels ------------------------------------

__global__ void k_init() {
    int i = blockIdx.x * blockDim.x + threadIdx.x;
    if (i < NN) {
        g_deg[i] = 1.0f;   // self-loop weight
        g_cnt[i] = 0;
    }
}

__global__ void k_degcnt(const int* __restrict__ ei, const float* __restrict__ ew) {
    int e = blockIdx.x * blockDim.x + threadIdx.x;
    if (e < EE) {
        int c = ei[EE + e];        // col (target)
        atomicAdd(&g_deg[c], ew[e]);
        atomicAdd(&g_cnt[c], 1);
    }
}

__global__ void k_dinv() {
    int i = blockIdx.x * blockDim.x + threadIdx.x;
    if (i < NN) g_dinv[i] = rsqrtf(g_deg[i]);   // deg >= 1 always (self loop)
}

// single-block exclusive scan of g_cnt -> g_rowptr / g_cursor
__global__ void k_scan() {
    __shared__ int sdata[1024];
    __shared__ int s_carry;
    int tid = threadIdx.x;
    if (tid == 0) s_carry = 0;
    __syncthreads();
    for (int base = 0; base < NN; base += 1024) {
        int i = base + tid;
        int v = (i < NN) ? g_cnt[i] : 0;
        sdata[tid] = v;
        __syncthreads();
        #pragma unroll
        for (int off = 1; off < 1024; off <<= 1) {
            int t = (tid >= off) ? sdata[tid - off] : 0;
            __syncthreads();
            sdata[tid] += t;
            __syncthreads();
        }
        int inc = sdata[tid];
        int carry = s_carry;
        int exc = carry + inc - v;
        if (i < NN) {
            g_rowptr[i] = exc;
            g_cursor[i] = exc;
        }
        __syncthreads();
        if (tid == 1023) s_carry = carry + inc;
        __syncthreads();
    }
    if (tid == 0) g_rowptr[NN] = EE;
}

__global__ void k_fill(const int* __restrict__ ei, const float* __restrict__ ew) {
    int e = blockIdx.x * blockDim.x + threadIdx.x;
    if (e < EE) {
        int r = ei[e];
        int c = ei[EE + e];
        float nrm = g_dinv[r] * ew[e] * g_dinv[c];
        int pos = atomicAdd(&g_cursor[c], 1);
        g_src[pos]  = r;
        g_norm[pos] = nrm;
    }
}

// ---------------- GEMM: xw[n,j] = sum_k h[n,k] * W[j*D+k] ------------------
// BM=64 rows, BN=128 cols (full), BK=32. 256 threads, each 8 rows x 4 cols.

#define BM 64
#define BK 32
#define SH_LD 36
#define SW_LD 132

__global__ __launch_bounds__(256) void k_gemm(const float* __restrict__ h,
                                              const float* __restrict__ W,
                                              float* __restrict__ out) {
    __shared__ float sh[BM][SH_LD];    // h tile  [row][k]
    __shared__ float sw[BK][SW_LD];    // W tile transposed [k][j]
    int block_row = blockIdx.x * BM;
    int t  = threadIdx.x;
    int rg = t >> 5;        // 0..7   row group (uniform in warp)
    int cg = t & 31;        // 0..31  col group

    float acc[8][4];
    #pragma unroll
    for (int i = 0; i < 8; i++)
        #pragma unroll
        for (int j = 0; j < 4; j++) acc[i][j] = 0.0f;

    for (int k0 = 0; k0 < DD; k0 += BK) {
        // load h tile: 64x32 floats = 512 float4; each thread 2
        #pragma unroll
        for (int i = 0; i < 2; i++) {
            int idx = t + i * 256;          // 0..511
            int r   = idx >> 3;             // 8 float4 per row
            int c4  = idx & 7;
            int gr  = block_row + r;
            float4 v = make_float4(0.f, 0.f, 0.f, 0.f);
            if (gr < NN)
                v = *(const float4*)&h[(size_t)gr * DD + k0 + c4 * 4];
            *(float4*)&sh[r][c4 * 4] = v;
        }
        // load W tile transposed: 128 j x 32 k = 1024 float4; each thread 4
        #pragma unroll
        for (int i = 0; i < 4; i++) {
            int idx = t + i * 256;          // 0..1023
            int j   = idx >> 3;
            int c4  = idx & 7;
            float4 v = *(const float4*)&W[(size_t)j * DD + k0 + c4 * 4];
            sw[c4 * 4 + 0][j] = v.x;
            sw[c4 * 4 + 1][j] = v.y;
            sw[c4 * 4 + 2][j] = v.z;
            sw[c4 * 4 + 3][j] = v.w;
        }
        __syncthreads();

        #pragma unroll
        for (int k = 0; k < BK; k++) {
            float4 bv = *(const float4*)&sw[k][cg * 4];
            #pragma unroll
            for (int i = 0; i < 8; i++) {
                float a = sh[rg * 8 + i][k];
                acc[i][0] += a * bv.x;
                acc[i][1] += a * bv.y;
                acc[i][2] += a * bv.z;
                acc[i][3] += a * bv.w;
            }
        }
        __syncthreads();
    }

    #pragma unroll
    for (int i = 0; i < 8; i++) {
        int gr = block_row + rg * 8 + i;
        if (gr < NN) {
            float4 v = make_float4(acc[i][0], acc[i][1], acc[i][2], acc[i][3]);
            *(float4*)&out[(size_t)gr * DD + cg * 4] = v;
        }
    }
}

// ---------------- fused aggregate + LayerNorm + ReLU + residual ------------
// one 128-thread block per destination node

__global__ __launch_bounds__(128) void k_agg_ln(const float* __restrict__ xw,
                                                const float* __restrict__ hin,
                                                const float* __restrict__ bias,
                                                const float* __restrict__ gamma,
                                                const float* __restrict__ beta,
                                                float* __restrict__ hout,
                                                int do_relu) {
    int n = blockIdx.x;
    int d = threadIdx.x;

    __shared__ int   s_src[128];
    __shared__ float s_nrm[128];
    __shared__ float s_red[4];

    float dv  = g_dinv[n];
    float acc = dv * dv * __ldg(&xw[(size_t)n * DD + d]) + __ldg(&bias[d]);

    int beg = g_rowptr[n], end = g_rowptr[n + 1];
    for (int c0 = beg; c0 < end; c0 += 128) {
        int m = end - c0;
        if (m > 128) m = 128;
        if (d < m) {
            s_src[d] = g_src[c0 + d];
            s_nrm[d] = g_norm[c0 + d];
        }
        __syncthreads();
        int j = 0;
        int m4 = m & ~3;
        for (; j < m4; j += 4) {
            float w0 = s_nrm[j + 0], w1 = s_nrm[j + 1];
            float w2 = s_nrm[j + 2], w3 = s_nrm[j + 3];
            float x0 = __ldg(&xw[(size_t)s_src[j + 0] * DD + d]);
            float x1 = __ldg(&xw[(size_t)s_src[j + 1] * DD + d]);
            float x2 = __ldg(&xw[(size_t)s_src[j + 2] * DD + d]);
            float x3 = __ldg(&xw[(size_t)s_src[j + 3] * DD + d]);
            acc += w0 * x0;
            acc += w1 * x1;
            acc += w2 * x2;
            acc += w3 * x3;
        }
        for (; j < m; j++)
            acc += s_nrm[j] * __ldg(&xw[(size_t)s_src[j] * DD + d]);
        __syncthreads();
    }

    // ---- LayerNorm over the 128 features (two-pass for accuracy) ----
    int lane = d & 31, warp = d >> 5;
    float s = acc;
    #pragma unroll
    for (int off = 16; off >= 1; off >>= 1) s += __shfl_xor_sync(0xffffffff, s, off);
    if (lane == 0) s_red[warp] = s;
    __syncthreads();
    float mu = (s_red[0] + s_red[1] + s_red[2] + s_red[3]) * (1.0f / 128.0f);

    float dvv = acc - mu;
    float q = dvv * dvv;
    #pragma unroll
    for (int off = 16; off >= 1; off >>= 1) q += __shfl_xor_sync(0xffffffff, q, off);
    __syncthreads();
    if (lane == 0) s_red[warp] = q;
    __syncthreads();
    float var = (s_red[0] + s_red[1] + s_red[2] + s_red[3]) * (1.0f / 128.0f);

    float y = dvv * rsqrtf(var + LN_EPS) * __ldg(&gamma[d]) + __ldg(&beta[d]);
    if (do_relu) y = fmaxf(y, 0.0f);
    y += __ldg(&hin[(size_t)n * DD + d]);
    hout[(size_t)n * DD + d] = y;
}

// ---------------- launch ----------------------------------------------------

extern "C" void kernel_launch(void* const* d_in, const int* in_sizes, int n_in,
                              void* d_out, int out_size) {
    const float* x      = (const float*)d_in[0];
    const int*   ei     = (const int*)  d_in[1];
    const float* ew     = (const float*)d_in[2];
    const float* Ws     = (const float*)d_in[3];
    const float* bs     = (const float*)d_in[4];
    const float* gammas = (const float*)d_in[5];
    const float* betas  = (const float*)d_in[6];
    float* out = (float*)d_out;

    float* xw = nullptr; cudaGetSymbolAddress((void**)&xw, g_xw);
    float* hA = nullptr; cudaGetSymbolAddress((void**)&hA, g_hA);
    float* hB = nullptr; cudaGetSymbolAddress((void**)&hB, g_hB);

    int gN = (NN + 255) / 256;
    int gE = (EE + 255) / 256;
    int gGemm = (NN + BM - 1) / BM;

    k_init<<<gN, 256>>>();
    k_degcnt<<<gE, 256>>>(ei, ew);
    k_dinv<<<gN, 256>>>();
    k_scan<<<1, 1024>>>();
    k_fill<<<gE, 256>>>(ei, ew);

    // layer 0: x -> hA
    k_gemm<<<gGemm, 256>>>(x, Ws + 0 * DD * DD, xw);
    k_agg_ln<<<NN, 128>>>(xw, x, bs + 0 * DD, gammas + 0 * DD, betas + 0 * DD, hA, 1);
    // layer 1: hA -> hB
    k_gemm<<<gGemm, 256>>>(hA, Ws + 1 * DD * DD, xw);
    k_agg_ln<<<NN, 128>>>(xw, hA, bs + 1 * DD, gammas + 1 * DD, betas + 1 * DD, hB, 1);
    // layer 2: hB -> out
    k_gemm<<<gGemm, 256>>>(hB, Ws + 2 * DD * DD, xw);
    k_agg_ln<<<NN, 128>>>(xw, hB, bs + 2 * DD, gammas + 2 * DD, betas + 2 * DD, out, 0);
}

// round 3
// speedup vs baseline: 1.1216x; 1.1216x over previous
#include <cuda_runtime.h>
#include <cuda_bf16.h>
#include <cstdint>

#define NN 50000
#define EE 1600000
#define DD 128
#define LN_EPS 1e-5f

// ---------------- scratch (static device globals) ---------------------------
__device__ float g_deg[NN];
__device__ int   g_cnt[NN];
__device__ int   g_rowptr[NN + 1];
__device__ int   g_cursor[NN];
__device__ int2  g_edge[EE];                    // (src, norm bits)
__device__ float g_xw[(size_t)NN * DD];
__device__ float g_hA[(size_t)NN * DD];
__device__ float g_hB[(size_t)NN * DD];
__device__ __nv_bfloat16 g_xhi[(size_t)NN * DD];
__device__ __nv_bfloat16 g_xlo[(size_t)NN * DD];
__device__ __nv_bfloat16 g_Whi[3 * DD * DD];
__device__ __nv_bfloat16 g_Wlo[3 * DD * DD];

__device__ __forceinline__ uint32_t smem_to_u32(const void* p) {
    uint32_t a;
    asm("{ .reg .u64 t; cvta.to.shared.u64 t, %1; cvt.u32.u64 %0, t; }" : "=r"(a) : "l"(p));
    return a;
}

// ---------------- combined conversion + init kernel -------------------------
// blocks [0,25000): x -> hi/lo ; [25000,25192): W -> hi/lo ; rest: init deg/cnt
__global__ __launch_bounds__(256) void k_conv(const float* __restrict__ x,
                                              const float* __restrict__ Ws) {
    int b = blockIdx.x, t = threadIdx.x;
    if (b < 25000) {
        int i = b * 256 + t;
        float v = x[i];
        __nv_bfloat16 hi = __float2bfloat16(v);
        g_xhi[i] = hi;
        g_xlo[i] = __float2bfloat16(v - __bfloat162float(hi));
    } else if (b < 25192) {
        int j = (b - 25000) * 256 + t;     // < 49152
        float v = Ws[j];
        __nv_bfloat16 hi = __float2bfloat16(v);
        g_Whi[j] = hi;
        g_Wlo[j] = __float2bfloat16(v - __bfloat162float(hi));
    } else {
        int i = (b - 25192) * 256 + t;
        if (i < NN) { g_deg[i] = 1.0f; g_cnt[i] = 0; }
    }
}

__global__ void k_degcnt(const int* __restrict__ ei, const float* __restrict__ ew) {
    int e = blockIdx.x * blockDim.x + threadIdx.x;
    if (e < EE) {
        int c = ei[EE + e];
        atomicAdd(&g_deg[c], ew[e]);
        atomicAdd(&g_cnt[c], 1);
    }
}

// single-block scan: 1024 threads x 8 elems/iter, warp-shuffle based
__global__ __launch_bounds__(1024) void k_scan() {
    __shared__ int s_w[32];
    __shared__ int s_carry;
    int tid = threadIdx.x, lane = tid & 31, wid = tid >> 5;
    if (tid == 0) s_carry = 0;
    __syncthreads();
    for (int base = 0; base < NN; base += 8192) {
        int i0 = base + tid * 8;
        int v[8], pref[8], p = 0;
        #pragma unroll
        for (int j = 0; j < 8; j++) {
            int idx = i0 + j;
            v[j] = (idx < NN) ? g_cnt[idx] : 0;
            p += v[j];
            pref[j] = p;
        }
        int t = p;
        #pragma unroll
        for (int off = 1; off < 32; off <<= 1) {
            int u = __shfl_up_sync(0xffffffffu, t, off);
            if (lane >= off) t += u;
        }
        if (lane == 31) s_w[wid] = t;
        __syncthreads();
        if (wid == 0) {
            int w = s_w[lane];
            #pragma unroll
            for (int off = 1; off < 32; off <<= 1) {
                int u = __shfl_up_sync(0xffffffffu, w, off);
                if (lane >= off) w += u;
            }
            s_w[lane] = w;
        }
        __syncthreads();
        int warpExcl = (wid == 0) ? 0 : s_w[wid - 1];
        int carry = s_carry;
        int myBase = carry + warpExcl + (t - p);
        #pragma unroll
        for (int j = 0; j < 8; j++) {
            int idx = i0 + j;
            if (idx < NN) {
                int e = myBase + pref[j] - v[j];
                g_rowptr[idx] = e;
                g_cursor[idx] = e;
            }
        }
        __syncthreads();
        if (tid == 1023) s_carry = carry + s_w[31];
        __syncthreads();
    }
    if (tid == 0) g_rowptr[NN] = EE;
}

__global__ void k_fill(const int* __restrict__ ei, const float* __restrict__ ew) {
    int e = blockIdx.x * blockDim.x + threadIdx.x;
    if (e < EE) {
        int r = ei[e];
        int c = ei[EE + e];
        float nrm = rsqrtf(g_deg[r]) * ew[e] * rsqrtf(g_deg[c]);
        int pos = atomicAdd(&g_cursor[c], 1);
        g_edge[pos] = make_int2(r, __float_as_int(nrm));
    }
}

// ---------------- mma.sync split-bf16 GEMM: out = A @ W^T -------------------
// Block tile: 128 rows x 128 cols, full K=128 resident in smem.
// 8 warps as 4x2: warp computes 32 rows x 64 cols.
// D = Ahi*Whi + Ahi*Wlo + Alo*Whi  (fp32 accum in registers).

#define PADB 136                         // bf16 units per smem row (272B, LDSM conflict-free)
#define TILE_B (128 * PADB * 2)          // 34816 bytes per tile
#define SMEM_MMA_TOTAL (4 * TILE_B)      // 139264

__device__ __forceinline__ void ldsm_x4(uint32_t* r, uint32_t addr) {
    asm volatile("ldmatrix.sync.aligned.m8n8.x4.shared.b16 {%0,%1,%2,%3}, [%4];"
                 : "=r"(r[0]), "=r"(r[1]), "=r"(r[2]), "=r"(r[3]) : "r"(addr));
}
__device__ __forceinline__ void mma_bf16(float* c, const uint32_t* a, const uint32_t* b) {
    asm volatile("mma.sync.aligned.m16n8k16.row.col.f32.bf16.bf16.f32 "
                 "{%0,%1,%2,%3}, {%4,%5,%6,%7}, {%8,%9}, {%0,%1,%2,%3};"
                 : "+f"(c[0]), "+f"(c[1]), "+f"(c[2]), "+f"(c[3])
                 : "r"(a[0]), "r"(a[1]), "r"(a[2]), "r"(a[3]), "r"(b[0]), "r"(b[1]));
}

__global__ __launch_bounds__(256) void k_mma(const __nv_bfloat16* __restrict__ Ahi,
                                             const __nv_bfloat16* __restrict__ Alo,
                                             const __nv_bfloat16* __restrict__ Whi,
                                             const __nv_bfloat16* __restrict__ Wlo,
                                             float* __restrict__ out) {
    extern __shared__ char smem[];
    uint32_t sbase = smem_to_u32(smem);
    int tid = threadIdx.x;
    int bm = blockIdx.x * 128;

    // ---- load 4 tiles (Ahi, Alo, Whi, Wlo), each 128x128 bf16, padded rows ----
    #pragma unroll
    for (int it = 0; it < 32; it++) {
        int idx = tid + it * 256;            // 0..8191
        int tile = idx >> 11;
        int g = idx & 2047;
        int r = g >> 4, c8 = g & 15;         // 16 uint4 per row
        uint32_t dst = (uint32_t)tile * TILE_B + ((uint32_t)r * PADB + (uint32_t)c8 * 8) * 2;
        uint4 v = make_uint4(0, 0, 0, 0);
        if (tile < 2) {
            int gr = bm + r;
            const __nv_bfloat16* bp = (tile == 0) ? Ahi : Alo;
            if (gr < NN) v = *(const uint4*)(bp + (size_t)gr * 128 + c8 * 8);
        } else {
            const __nv_bfloat16* bp = (tile == 2) ? Whi : Wlo;
            v = *(const uint4*)(bp + r * 128 + c8 * 8);
        }
        *(uint4*)(smem + dst) = v;
    }
    __syncthreads();

    int lane = tid & 31, warp = tid >> 5;
    int wm = warp >> 1;                      // 0..3 -> row offset 32*wm
    int wn = warp & 1;                       // 0..1 -> col offset 64*wn

    // ldmatrix lane base offsets (bytes within a tile), before k advance
    // A frag mi: rows m0 + (lane&15), k off 8*(lane>>4)
    uint32_t aoff[2];
    #pragma unroll
    for (int mi = 0; mi < 2; mi++) {
        int row = wm * 32 + mi * 16 + (lane & 15);
        aoff[mi] = ((uint32_t)row * PADB + (uint32_t)(lane >> 4) * 8) * 2;
    }
    // B pair pi covers n-frags 2*pi, 2*pi+1: row n0 + (lane&7) + 8*((lane>>4)&1), k off 8*((lane>>3)&1)
    uint32_t boff[4];
    #pragma unroll
    for (int pi = 0; pi < 4; pi++) {
        int row = wn * 64 + pi * 16 + (lane & 7) + 8 * ((lane >> 4) & 1);
        boff[pi] = ((uint32_t)row * PADB + (uint32_t)((lane >> 3) & 1) * 8) * 2;
    }

    uint32_t sAhi = sbase + 0 * TILE_B, sAlo = sbase + 1 * TILE_B;
    uint32_t sWhi = sbase + 2 * TILE_B, sWlo = sbase + 3 * TILE_B;

    float C[2][8][4];
    #pragma unroll
    for (int mi = 0; mi < 2; mi++)
        #pragma unroll
        for (int ni = 0; ni < 8; ni++)
            #pragma unroll
            for (int q = 0; q < 4; q++) C[mi][ni][q] = 0.0f;

    #pragma unroll
    for (int ks = 0; ks < 8; ks++) {
        uint32_t kadv = (uint32_t)ks * 32;   // 16 bf16 = 32 bytes
        uint32_t ahi[2][4], alo[2][4], bhi[4][4], blo[4][4];
        #pragma unroll
        for (int mi = 0; mi < 2; mi++) {
            ldsm_x4(ahi[mi], sAhi + aoff[mi] + kadv);
            ldsm_x4(alo[mi], sAlo + aoff[mi] + kadv);
        }
        #pragma unroll
        for (int pi = 0; pi < 4; pi++) {
            ldsm_x4(bhi[pi], sWhi + boff[pi] + kadv);
            ldsm_x4(blo[pi], sWlo + boff[pi] + kadv);
        }
        #pragma unroll
        for (int mi = 0; mi < 2; mi++) {
            #pragma unroll
            for (int ni = 0; ni < 8; ni++) {
                const uint32_t* bh = &bhi[ni >> 1][(ni & 1) * 2];
                const uint32_t* bl = &blo[ni >> 1][(ni & 1) * 2];
                mma_bf16(C[mi][ni], ahi[mi], bh);   // hi*hi
                mma_bf16(C[mi][ni], ahi[mi], bl);   // hi*lo
                mma_bf16(C[mi][ni], alo[mi], bh);   // lo*hi
            }
        }
    }

    // ---- epilogue: direct float2 stores ----
    int g = lane >> 2, ctg = lane & 3;
    #pragma unroll
    for (int mi = 0; mi < 2; mi++) {
        int r0 = bm + wm * 32 + mi * 16 + g;
        #pragma unroll
        for (int ni = 0; ni < 8; ni++) {
            int col = wn * 64 + ni * 8 + ctg * 2;
            if (r0 < NN)
                *(float2*)&out[(size_t)r0 * 128 + col] = make_float2(C[mi][ni][0], C[mi][ni][1]);
            if (r0 + 8 < NN)
                *(float2*)&out[(size_t)(r0 + 8) * 128 + col] = make_float2(C[mi][ni][2], C[mi][ni][3]);
        }
    }
}

// ---------------- fused aggregate + LN + ReLU + residual (+bf16 conv) -------
__global__ __launch_bounds__(128) void k_agg(const float* __restrict__ xw,
                                             const float* __restrict__ hin,
                                             const float* __restrict__ bias,
                                             const float* __restrict__ gamma,
                                             const float* __restrict__ beta,
                                             float* __restrict__ hout,
                                             int flags) {   // bit0 relu, bit1 conv
    int n = blockIdx.x;
    int d = threadIdx.x;

    __shared__ int   s_src[128];
    __shared__ float s_nrm[128];
    __shared__ float s_red[4];

    float invdeg = 1.0f / g_deg[n];
    float acc = invdeg * __ldg(&xw[(size_t)n * DD + d]) + __ldg(&bias[d]);

    int beg = g_rowptr[n], end = g_rowptr[n + 1];
    for (int c0 = beg; c0 < end; c0 += 128) {
        int m = end - c0;
        if (m > 128) m = 128;
        if (d < m) {
            int2 e = g_edge[c0 + d];
            s_src[d] = e.x;
            s_nrm[d] = __int_as_float(e.y);
        }
        __syncthreads();
        int j = 0;
        int m4 = m & ~3;
        for (; j < m4; j += 4) {
            float w0 = s_nrm[j + 0], w1 = s_nrm[j + 1];
            float w2 = s_nrm[j + 2], w3 = s_nrm[j + 3];
            float x0 = __ldg(&xw[(size_t)s_src[j + 0] * DD + d]);
            float x1 = __ldg(&xw[(size_t)s_src[j + 1] * DD + d]);
            float x2 = __ldg(&xw[(size_t)s_src[j + 2] * DD + d]);
            float x3 = __ldg(&xw[(size_t)s_src[j + 3] * DD + d]);
            acc += w0 * x0;
            acc += w1 * x1;
            acc += w2 * x2;
            acc += w3 * x3;
        }
        for (; j < m; j++)
            acc += s_nrm[j] * __ldg(&xw[(size_t)s_src[j] * DD + d]);
        __syncthreads();
    }

    // LayerNorm over 128 features
    int lane = d & 31, warp = d >> 5;
    float s = acc;
    #pragma unroll
    for (int off = 16; off >= 1; off >>= 1) s += __shfl_xor_sync(0xffffffff, s, off);
    if (lane == 0) s_red[warp] = s;
    __syncthreads();
    float mu = (s_red[0] + s_red[1] + s_red[2] + s_red[3]) * (1.0f / 128.0f);

    float dvv = acc - mu;
    float q = dvv * dvv;
    #pragma unroll
    for (int off = 16; off >= 1; off >>= 1) q += __shfl_xor_sync(0xffffffff, q, off);
    __syncthreads();
    if (lane == 0) s_red[warp] = q;
    __syncthreads();
    float var = (s_red[0] + s_red[1] + s_red[2] + s_red[3]) * (1.0f / 128.0f);

    float y = dvv * rsqrtf(var + LN_EPS) * __ldg(&gamma[d]) + __ldg(&beta[d]);
    if (flags & 1) y = fmaxf(y, 0.0f);
    y += __ldg(&hin[(size_t)n * DD + d]);
    hout[(size_t)n * DD + d] = y;
    if (flags & 2) {
        __nv_bfloat16 hi = __float2bfloat16(y);
        size_t i = (size_t)n * DD + d;
        g_xhi[i] = hi;
        g_xlo[i] = __float2bfloat16(y - __bfloat162float(hi));
    }
}

// ---------------- launch ----------------------------------------------------
extern "C" void kernel_launch(void* const* d_in, const int* in_sizes, int n_in,
                              void* d_out, int out_size) {
    const float* x      = (const float*)d_in[0];
    const int*   ei     = (const int*)  d_in[1];
    const float* ew     = (const float*)d_in[2];
    const float* Ws     = (const float*)d_in[3];
    const float* bs     = (const float*)d_in[4];
    const float* gammas = (const float*)d_in[5];
    const float* betas  = (const float*)d_in[6];
    float* out = (float*)d_out;

    float* xw = nullptr; cudaGetSymbolAddress((void**)&xw, g_xw);
    float* hA = nullptr; cudaGetSymbolAddress((void**)&hA, g_hA);
    float* hB = nullptr; cudaGetSymbolAddress((void**)&hB, g_hB);
    __nv_bfloat16* xhi = nullptr; cudaGetSymbolAddress((void**)&xhi, g_xhi);
    __nv_bfloat16* xlo = nullptr; cudaGetSymbolAddress((void**)&xlo, g_xlo);
    __nv_bfloat16* Whi = nullptr; cudaGetSymbolAddress((void**)&Whi, g_Whi);
    __nv_bfloat16* Wlo = nullptr; cudaGetSymbolAddress((void**)&Wlo, g_Wlo);

    cudaFuncSetAttribute(k_mma, cudaFuncAttributeMaxDynamicSharedMemorySize, SMEM_MMA_TOTAL);

    int gE = (EE + 255) / 256;
    int gConv = 25192 + (NN + 255) / 256;
    int gMma = (NN + 127) / 128;              // 391

    k_conv<<<gConv, 256>>>(x, Ws);
    k_degcnt<<<gE, 256>>>(ei, ew);
    k_scan<<<1, 1024>>>();
    k_fill<<<gE, 256>>>(ei, ew);

    // layer 0: x -> hA   (k_agg L0 at launch index 5 for ncu capture)
    k_mma<<<gMma, 256, SMEM_MMA_TOTAL>>>(xhi, xlo, Whi + 0 * DD * DD, Wlo + 0 * DD * DD, xw);
    k_agg<<<NN, 128>>>(xw, x, bs + 0 * DD, gammas + 0 * DD, betas + 0 * DD, hA, 1 | 2);
    // layer 1: hA -> hB
    k_mma<<<gMma, 256, SMEM_MMA_TOTAL>>>(xhi, xlo, Whi + 1 * DD * DD, Wlo + 1 * DD * DD, xw);
    k_agg<<<NN, 128>>>(xw, hA, bs + 1 * DD, gammas + 1 * DD, betas + 1 * DD, hB, 1 | 2);
    // layer 2: hB -> out
    k_mma<<<gMma, 256, SMEM_MMA_TOTAL>>>(xhi, xlo, Whi + 2 * DD * DD, Wlo + 2 * DD * DD, xw);
    k_agg<<<NN, 128>>>(xw, hB, bs + 2 * DD, gammas + 2 * DD, betas + 2 * DD, out, 0);
}